// round 15
// baseline (speedup 1.0000x reference)
#include <cuda_runtime.h>
#include <cuda_fp16.h>
#include <cstdint>

// ---------------------------------------------------------------------------
// Problem constants
// ---------------------------------------------------------------------------
#define B_  8192
#define D_  1024
#define O_  1024
#define E_  8

// GEMM tiling: CTA 128x128, 8 warps of 64x32, K=64 per stage, 2 CTAs/SM
#define BM 128
#define BN 128
#define KSTG 64
#define NST (E_ * D_ / KSTG)        // 128 stages (16 per expert)
#define A_BYTES (BM * 128)          // 16 KB
#define B_BYTES (BN * 128)          // 16 KB
#define STAGEB (A_BYTES + B_BYTES)  // 32 KB
#define NSTAGE 3

// SMEM layout
#define SM_GS 0                     // gates [8][128] f32 = 4 KB
#define SM_BE 4096                  // bias  [8][128] f32 = 4 KB
#define SM_ST 8192
#define SMEM_TOTAL (SM_ST + NSTAGE * STAGEB)   // 106496 (x2 CTAs fits 228KB)

// ---------------------------------------------------------------------------
// Scratch (device globals — no allocation)
// ---------------------------------------------------------------------------
__device__ float g_gates[B_ * E_];
__device__ __align__(16) __half g_xh[(size_t)B_ * D_];   // fp16 x, single copy
__device__ __align__(16) __half g_wt[E_ * O_ * D_];      // [e][n][k] K-major

// ---------------------------------------------------------------------------
// Helpers
// ---------------------------------------------------------------------------
__device__ __forceinline__ uint32_t smem_u32(const void* p) {
    uint32_t a;
    asm("{ .reg .u64 t; cvta.to.shared.u64 t, %1; cvt.u32.u64 %0, t; }" : "=r"(a) : "l"(p));
    return a;
}
#define SWZ(x) ((x) ^ (((x) >> 3) & 0x70))

__device__ __forceinline__ void cpa16(uint32_t dst, const void* src) {
    asm volatile("cp.async.cg.shared.global [%0], [%1], 16;" :: "r"(dst), "l"(src) : "memory");
}

#define LDSM4(r, addr) \
    asm volatile("ldmatrix.sync.aligned.m8n8.x4.shared.b16 {%0,%1,%2,%3}, [%4];" \
        : "=r"((r)[0]), "=r"((r)[1]), "=r"((r)[2]), "=r"((r)[3]) : "r"(addr))

#define MMA16816(c, a, b) \
    asm volatile("mma.sync.aligned.m16n8k16.row.col.f32.f16.f16.f32 " \
        "{%0,%1,%2,%3}, {%4,%5,%6,%7}, {%8,%9}, {%0,%1,%2,%3};" \
        : "+f"((c)[0]), "+f"((c)[1]), "+f"((c)[2]), "+f"((c)[3]) \
        : "r"((a)[0]), "r"((a)[1]), "r"((a)[2]), "r"((a)[3]), \
          "r"((b)[0]), "r"((b)[1]))

#define MULH2(d, a, b) \
    asm("mul.rn.f16x2 %0, %1, %2;" : "=r"(d) : "r"(a), "r"(b))

// ---------------------------------------------------------------------------
// Kernel 1: fused gating + x->fp16 convert (single copy, no gate folding)
// ---------------------------------------------------------------------------
__global__ void gates_xh_kernel(const float* __restrict__ x,
                                const float* __restrict__ Wg,
                                const float* __restrict__ bg) {
    int row = (blockIdx.x * blockDim.x + threadIdx.x) >> 5;
    int lane = threadIdx.x & 31;
    if (row >= B_) return;
    const float* xr = x + (size_t)row * D_;

    float acc[E_];
#pragma unroll
    for (int e = 0; e < E_; e++) acc[e] = 0.f;

    // gating dot products + fp16 conversion in the same x sweep
#pragma unroll
    for (int it = 0; it < 8; it++) {
        int idx = lane + it * 32;                       // float4 index 0..255
        float4 v = reinterpret_cast<const float4*>(xr)[idx];
        __half h[4] = { __float2half_rn(v.x), __float2half_rn(v.y),
                        __float2half_rn(v.z), __float2half_rn(v.w) };
        *reinterpret_cast<uint64_t*>(&g_xh[(size_t)row * D_ + idx * 4]) =
            *reinterpret_cast<uint64_t*>(h);
        const float* w0 = Wg + (idx * 4) * E_;
        float vv[4] = {v.x, v.y, v.z, v.w};
#pragma unroll
        for (int c = 0; c < 4; c++) {
            const float4* w4 = reinterpret_cast<const float4*>(w0 + c * E_);
            float4 wa = w4[0], wb = w4[1];
            acc[0] += vv[c] * wa.x; acc[1] += vv[c] * wa.y;
            acc[2] += vv[c] * wa.z; acc[3] += vv[c] * wa.w;
            acc[4] += vv[c] * wb.x; acc[5] += vv[c] * wb.y;
            acc[6] += vv[c] * wb.z; acc[7] += vv[c] * wb.w;
        }
    }
#pragma unroll
    for (int e = 0; e < E_; e++)
#pragma unroll
        for (int off = 16; off; off >>= 1)
            acc[e] += __shfl_xor_sync(0xffffffffu, acc[e], off);

    if (lane == 0) {
        float m = -1e30f;
#pragma unroll
        for (int e = 0; e < E_; e++) { acc[e] += bg[e]; m = fmaxf(m, acc[e]); }
        float s = 0.f;
#pragma unroll
        for (int e = 0; e < E_; e++) { acc[e] = expf(acc[e] - m); s += acc[e]; }
        float inv = 1.f / s;
#pragma unroll
        for (int e = 0; e < E_; e++) g_gates[row * E_ + e] = acc[e] * inv;
    }
}

// ---------------------------------------------------------------------------
// Kernel 2: transpose We[e][k][n] -> fp16 WeT[e][n][k]  (validated)
// ---------------------------------------------------------------------------
__global__ void wt_kernel(const float* __restrict__ We) {
    __shared__ float t[32][33];
    int e = blockIdx.z;
    int k0 = blockIdx.y * 32, n0 = blockIdx.x * 32;
    int tx = threadIdx.x, ty = threadIdx.y;
    const float* base = We + ((size_t)e << 20);
#pragma unroll
    for (int j = 0; j < 4; j++)
        t[ty + j * 8][tx] = base[(size_t)(k0 + ty + j * 8) * O_ + n0 + tx];
    __syncthreads();
    size_t ob = ((size_t)e << 20);
#pragma unroll
    for (int j = 0; j < 4; j++)
        g_wt[ob + (size_t)(n0 + ty + j * 8) * D_ + k0 + tx] =
            __float2half_rn(t[tx][ty + j * 8]);
}

// ---------------------------------------------------------------------------
// Kernel 3: fused MoE GEMM — gates folded into A fragments in registers.
//   out[b, n] = sum_{e,k} (g[b][e]*xh[b][k]) * wt[e][n][k] + sum_e g[b][e]*be[e][n]
// ---------------------------------------------------------------------------
__global__ __launch_bounds__(256, 2)
void moe_fp16_kernel(const float* __restrict__ be, float* __restrict__ out) {
    extern __shared__ char smem[];
    const uint32_t sb = smem_u32(smem);
    const int tid = threadIdx.x;
    const int lane = tid & 31;
    const int wid = tid >> 5;
    const int warp_m = wid >> 2;        // 0..1  (64-row slabs)
    const int warp_n = wid & 3;         // 0..3  (32-col slabs)
    const int m0 = blockIdx.y * BM;
    const int n0 = blockIdx.x * BN;

    float* gs  = reinterpret_cast<float*>(smem + SM_GS);   // [8][128]
    float* bes = reinterpret_cast<float*>(smem + SM_BE);   // [8][128]
    for (int i = tid; i < E_ * BM; i += 256)
        gs[i] = g_gates[(size_t)(m0 + (i & 127)) * E_ + (i >> 7)];
    for (int i = tid; i < E_ * BN; i += 256)
        bes[i] = be[(i >> 7) * O_ + n0 + (i & 127)];

    float acc[4][4][4];
#pragma unroll
    for (int a = 0; a < 4; a++)
#pragma unroll
        for (int b = 0; b < 4; b++)
#pragma unroll
            for (int c = 0; c < 4; c++) acc[a][b][c] = 0.f;

    // stage loader: 8 x 16B cp.async per thread (A 16 KB + B 16 KB)
    // A source is expert-independent (single xh copy -> L2-resident).
    auto issue = [&](int s) {
        const int e = s >> 4, kc = s & 15, koff = kc * KSTG;
        const uint32_t stg = sb + SM_ST + (s % NSTAGE) * STAGEB;
#pragma unroll
        for (int i = 0; i < 8; i++) {
            int c = tid + i * 256;
            if (c < 1024) {                 // A: 128 rows x 64 k
                int r = c >> 3, k16 = c & 7;
                uint32_t dst = stg + SWZ(r * 128 + k16 * 16);
                cpa16(dst, g_xh + ((size_t)(m0 + r) * D_ + koff + k16 * 8));
            } else {                        // B: 128 rows x 64 k
                int cb = c - 1024;
                int r = cb >> 3, k16 = cb & 7;
                uint32_t dst = stg + A_BYTES + SWZ(r * 128 + k16 * 16);
                cpa16(dst, g_wt + (((size_t)e * O_ + n0 + r) * D_ + koff + k16 * 8));
            }
        }
        asm volatile("cp.async.commit_group;" ::: "memory");
    };

    issue(0); issue(1);

    // ldmatrix lane address components
    const int a_row = lane & 15;
    const int a_kb  = lane >> 4;
    const int b_row = (lane & 7) + ((lane >> 4) << 3);
    const int b_kb  = (lane >> 3) & 1;

    uint32_t gh2[4][2];                 // broadcast fp16x2 gates, per mf x {row, row+8}

    for (int s = 0; s < NST; s++) {
        asm volatile("cp.async.wait_group 1;" ::: "memory");
        __syncthreads();
        if (s + 2 < NST) issue(s + 2);

        if ((s & 15) == 0) {            // expert boundary: refresh gate regs
            const int e = s >> 4;
#pragma unroll
            for (int mf = 0; mf < 4; mf++) {
                int rl = warp_m * 64 + mf * 16 + (lane >> 2);
                __half2 h0 = __float2half2_rn(gs[e * BM + rl]);
                __half2 h1 = __float2half2_rn(gs[e * BM + rl + 8]);
                gh2[mf][0] = *reinterpret_cast<uint32_t*>(&h0);
                gh2[mf][1] = *reinterpret_cast<uint32_t*>(&h1);
            }
        }

        const uint32_t stg = sb + SM_ST + (s % NSTAGE) * STAGEB;

#pragma unroll
        for (int kk = 0; kk < 4; kk++) {      // 4 k16 steps
            uint32_t a[4][4], bf[4][2];
#pragma unroll
            for (int mf = 0; mf < 4; mf++) {
                int row = warp_m * 64 + mf * 16 + a_row;
                LDSM4(a[mf], stg + SWZ(row * 128 + kk * 32 + a_kb * 16));
                // fold gate: regs {0,2} = row r, regs {1,3} = row r+8
                MULH2(a[mf][0], a[mf][0], gh2[mf][0]);
                MULH2(a[mf][1], a[mf][1], gh2[mf][1]);
                MULH2(a[mf][2], a[mf][2], gh2[mf][0]);
                MULH2(a[mf][3], a[mf][3], gh2[mf][1]);
            }
#pragma unroll
            for (int nf2 = 0; nf2 < 2; nf2++) {
                int n = warp_n * 32 + nf2 * 16 + b_row;
                uint32_t t[4];
                LDSM4(t, stg + A_BYTES + SWZ(n * 128 + kk * 32 + b_kb * 16));
                bf[nf2 * 2][0] = t[0]; bf[nf2 * 2][1] = t[1];
                bf[nf2 * 2 + 1][0] = t[2]; bf[nf2 * 2 + 1][1] = t[3];
            }
#pragma unroll
            for (int mf = 0; mf < 4; mf++)
#pragma unroll
                for (int nf = 0; nf < 4; nf++)
                    MMA16816(acc[mf][nf], a[mf], bf[nf]);
        }
    }

    // epilogue: bias (sum_e g_e * be_e) + store
#pragma unroll
    for (int mf = 0; mf < 4; mf++) {
        int rl = warp_m * 64 + mf * 16 + (lane >> 2);
        size_t row_g = (size_t)(m0 + rl);
#pragma unroll
        for (int nf = 0; nf < 4; nf++) {
            int col = warp_n * 32 + nf * 8 + (lane & 3) * 2;
            float b00 = 0.f, b01 = 0.f, b10 = 0.f, b11 = 0.f;
#pragma unroll
            for (int e = 0; e < E_; e++) {
                float gl = gs[e * BM + rl], gh = gs[e * BM + rl + 8];
                float c0 = bes[e * BN + col], c1 = bes[e * BN + col + 1];
                b00 += gl * c0; b01 += gl * c1;
                b10 += gh * c0; b11 += gh * c1;
            }
            *reinterpret_cast<float2*>(out + row_g * O_ + n0 + col) =
                make_float2(acc[mf][nf][0] + b00, acc[mf][nf][1] + b01);
            *reinterpret_cast<float2*>(out + (row_g + 8) * O_ + n0 + col) =
                make_float2(acc[mf][nf][2] + b10, acc[mf][nf][3] + b11);
        }
    }
}

// ---------------------------------------------------------------------------
extern "C" void kernel_launch(void* const* d_in, const int* in_sizes, int n_in,
                              void* d_out, int out_size) {
    const float* x  = (const float*)d_in[0];   // [8192, 1024]
    const float* Wg = (const float*)d_in[1];   // [1024, 8]
    const float* bg = (const float*)d_in[2];   // [8]
    const float* We = (const float*)d_in[3];   // [8, 1024, 1024]
    const float* be = (const float*)d_in[4];   // [8, 1024]
    float* out = (float*)d_out;                // [8192, 1024]

    cudaFuncSetAttribute(moe_fp16_kernel,
                         cudaFuncAttributeMaxDynamicSharedMemorySize, SMEM_TOTAL);

    gates_xh_kernel<<<B_ / 8, 256>>>(x, Wg, bg);
    wt_kernel<<<dim3(O_ / 32, D_ / 32, E_), dim3(32, 8)>>>(We);

    dim3 grid(O_ / BN, B_ / BM);               // (8, 64) = 512 CTAs
    moe_fp16_kernel<<<grid, 256, SMEM_TOTAL>>>(be, out);
}

// round 16
// speedup vs baseline: 1.2017x; 1.2017x over previous
#include <cuda_runtime.h>
#include <cuda_fp16.h>
#include <cstdint>

// ---------------------------------------------------------------------------
// Problem constants
// ---------------------------------------------------------------------------
#define B_  8192
#define D_  1024
#define O_  1024
#define E_  8

// GEMM tiling: CTA 128x128 with 4 warps of 64x64, K=64 per stage, 2 CTAs/SM
#define BM 128
#define BN 128
#define KSTG 64
#define NST (E_ * D_ / KSTG)        // 128 stages (16 per expert)
#define A_BYTES (BM * 128)          // 16 KB
#define B_BYTES (BN * 128)          // 16 KB
#define STAGEB (A_BYTES + B_BYTES)  // 32 KB
#define NSTAGE 3
#define THREADS 128

// SMEM layout
#define SM_GS 0                     // gates [8][128] f32 = 4 KB
#define SM_BE 4096                  // bias  [8][128] f32 = 4 KB
#define SM_ST 8192
#define SMEM_TOTAL (SM_ST + NSTAGE * STAGEB)   // 106496 (x2 CTAs fits)

// ---------------------------------------------------------------------------
// Scratch (device globals — no allocation)
// ---------------------------------------------------------------------------
__device__ float g_gates[B_ * E_];
__device__ __align__(16) __half g_gx[(size_t)E_ * B_ * D_];  // gate-scaled x, [e][b][d]
__device__ __align__(16) __half g_wt[E_ * O_ * D_];          // [e][n][k] K-major

// ---------------------------------------------------------------------------
// Helpers
// ---------------------------------------------------------------------------
__device__ __forceinline__ uint32_t smem_u32(const void* p) {
    uint32_t a;
    asm("{ .reg .u64 t; cvta.to.shared.u64 t, %1; cvt.u32.u64 %0, t; }" : "=r"(a) : "l"(p));
    return a;
}
#define SWZ(x) ((x) ^ (((x) >> 3) & 0x70))

__device__ __forceinline__ void cpa16(uint32_t dst, const void* src) {
    asm volatile("cp.async.cg.shared.global [%0], [%1], 16;" :: "r"(dst), "l"(src) : "memory");
}

#define LDSM4(r, addr) \
    asm volatile("ldmatrix.sync.aligned.m8n8.x4.shared.b16 {%0,%1,%2,%3}, [%4];" \
        : "=r"((r)[0]), "=r"((r)[1]), "=r"((r)[2]), "=r"((r)[3]) : "r"(addr))

#define MMA16816(c, a, b) \
    asm volatile("mma.sync.aligned.m16n8k16.row.col.f32.f16.f16.f32 " \
        "{%0,%1,%2,%3}, {%4,%5,%6,%7}, {%8,%9}, {%0,%1,%2,%3};" \
        : "+f"((c)[0]), "+f"((c)[1]), "+f"((c)[2]), "+f"((c)[3]) \
        : "r"((a)[0]), "r"((a)[1]), "r"((a)[2]), "r"((a)[3]), \
          "r"((b)[0]), "r"((b)[1]))

// ---------------------------------------------------------------------------
// Kernel 1: fused gating + prescale (round-14 validated version).
// One warp per row; butterfly leaves gates in all lanes; writes gx[e][b][d].
// ---------------------------------------------------------------------------
__global__ void gates_prescale_kernel(const float* __restrict__ x,
                                      const float* __restrict__ Wg,
                                      const float* __restrict__ bg) {
    int row = (blockIdx.x * blockDim.x + threadIdx.x) >> 5;
    int lane = threadIdx.x & 31;
    if (row >= B_) return;
    const float* xr = x + (size_t)row * D_;

    float acc[E_];
#pragma unroll
    for (int e = 0; e < E_; e++) acc[e] = 0.f;
    for (int d = lane; d < D_; d += 32) {
        float xv = xr[d];
        const float4* w4 = reinterpret_cast<const float4*>(Wg + d * E_);
        float4 w0 = w4[0], w1 = w4[1];
        acc[0] += xv * w0.x; acc[1] += xv * w0.y;
        acc[2] += xv * w0.z; acc[3] += xv * w0.w;
        acc[4] += xv * w1.x; acc[5] += xv * w1.y;
        acc[6] += xv * w1.z; acc[7] += xv * w1.w;
    }
#pragma unroll
    for (int e = 0; e < E_; e++)
#pragma unroll
        for (int off = 16; off; off >>= 1)
            acc[e] += __shfl_xor_sync(0xffffffffu, acc[e], off);

    float m = -1e30f;
#pragma unroll
    for (int e = 0; e < E_; e++) { acc[e] += bg[e]; m = fmaxf(m, acc[e]); }
    float s = 0.f;
#pragma unroll
    for (int e = 0; e < E_; e++) { acc[e] = expf(acc[e] - m); s += acc[e]; }
    float inv = 1.f / s;
#pragma unroll
    for (int e = 0; e < E_; e++) acc[e] *= inv;
    if (lane == 0) {
#pragma unroll
        for (int e = 0; e < E_; e++) g_gates[row * E_ + e] = acc[e];
    }

#pragma unroll
    for (int it = 0; it < 8; it++) {
        int idx = lane + it * 32;                       // float4 index 0..255
        float4 v = reinterpret_cast<const float4*>(xr)[idx];
#pragma unroll
        for (int e = 0; e < E_; e++) {
            float g = acc[e];
            __half h[4] = { __float2half_rn(g * v.x), __float2half_rn(g * v.y),
                            __float2half_rn(g * v.z), __float2half_rn(g * v.w) };
            size_t o = ((size_t)e * B_ + row) * D_ + idx * 4;
            *reinterpret_cast<uint64_t*>(&g_gx[o]) = *reinterpret_cast<uint64_t*>(h);
        }
    }
}

// ---------------------------------------------------------------------------
// Kernel 2: transpose We[e][k][n] -> fp16 WeT[e][n][k]  (validated)
// ---------------------------------------------------------------------------
__global__ void wt_kernel(const float* __restrict__ We) {
    __shared__ float t[32][33];
    int e = blockIdx.z;
    int k0 = blockIdx.y * 32, n0 = blockIdx.x * 32;
    int tx = threadIdx.x, ty = threadIdx.y;
    const float* base = We + ((size_t)e << 20);
#pragma unroll
    for (int j = 0; j < 4; j++)
        t[ty + j * 8][tx] = base[(size_t)(k0 + ty + j * 8) * O_ + n0 + tx];
    __syncthreads();
    size_t ob = ((size_t)e << 20);
#pragma unroll
    for (int j = 0; j < 4; j++)
        g_wt[ob + (size_t)(n0 + ty + j * 8) * D_ + k0 + tx] =
            __float2half_rn(t[tx][ty + j * 8]);
}

// ---------------------------------------------------------------------------
// Kernel 3: fused MoE GEMM — 4 warps of 64x64, 2 CTAs/SM.
//   out[b, n] = sum_{e,k} gx[e][b][k] * wt[e][n][k] + sum_e g[b][e]*be[e][n]
// ---------------------------------------------------------------------------
__global__ __launch_bounds__(THREADS, 2)
void moe_fp16_kernel(const float* __restrict__ be, float* __restrict__ out) {
    extern __shared__ char smem[];
    const uint32_t sb = smem_u32(smem);
    const int tid = threadIdx.x;
    const int lane = tid & 31;
    const int wid = tid >> 5;
    const int warp_m = wid >> 1;        // 0..1  (64-row slabs)
    const int warp_n = wid & 1;         // 0..1  (64-col slabs)
    const int m0 = blockIdx.y * BM;
    const int n0 = blockIdx.x * BN;

    float* gs  = reinterpret_cast<float*>(smem + SM_GS);   // [8][128]
    float* bes = reinterpret_cast<float*>(smem + SM_BE);   // [8][128]
    for (int i = tid; i < E_ * BM; i += THREADS)
        gs[i] = g_gates[(size_t)(m0 + (i & 127)) * E_ + (i >> 7)];
    for (int i = tid; i < E_ * BN; i += THREADS)
        bes[i] = be[(i >> 7) * O_ + n0 + (i & 127)];

    float acc[4][8][4];
#pragma unroll
    for (int a = 0; a < 4; a++)
#pragma unroll
        for (int b = 0; b < 8; b++)
#pragma unroll
            for (int c = 0; c < 4; c++) acc[a][b][c] = 0.f;

    // stage loader: 16 x 16B cp.async per thread (A 16 KB + B 16 KB)
    auto issue = [&](int s) {
        const int e = s >> 4, kc = s & 15, koff = kc * KSTG;
        const uint32_t stg = sb + SM_ST + (s % NSTAGE) * STAGEB;
#pragma unroll
        for (int i = 0; i < 16; i++) {
            int c = tid + i * THREADS;
            if (c < 1024) {                 // A: 128 rows x 64 k
                int r = c >> 3, k16 = c & 7;
                uint32_t dst = stg + SWZ(r * 128 + k16 * 16);
                cpa16(dst, g_gx + (((size_t)e * B_ + m0 + r) * D_ + koff + k16 * 8));
            } else {                        // B: 128 rows x 64 k
                int cb = c - 1024;
                int r = cb >> 3, k16 = cb & 7;
                uint32_t dst = stg + A_BYTES + SWZ(r * 128 + k16 * 16);
                cpa16(dst, g_wt + (((size_t)e * O_ + n0 + r) * D_ + koff + k16 * 8));
            }
        }
        asm volatile("cp.async.commit_group;" ::: "memory");
    };

    issue(0); issue(1);

    // ldmatrix lane address components
    const int a_row = lane & 15;
    const int a_kb  = lane >> 4;
    const int b_row = (lane & 7) + ((lane >> 4) << 3);
    const int b_kb  = (lane >> 3) & 1;

    for (int s = 0; s < NST; s++) {
        asm volatile("cp.async.wait_group 1;" ::: "memory");
        __syncthreads();
        if (s + 2 < NST) issue(s + 2);

        const uint32_t stg = sb + SM_ST + (s % NSTAGE) * STAGEB;

#pragma unroll
        for (int kk = 0; kk < 4; kk++) {      // 4 k16 steps
            uint32_t a[4][4], bf[8][2];
#pragma unroll
            for (int mf = 0; mf < 4; mf++) {
                int row = warp_m * 64 + mf * 16 + a_row;
                LDSM4(a[mf], stg + SWZ(row * 128 + kk * 32 + a_kb * 16));
            }
#pragma unroll
            for (int nf2 = 0; nf2 < 4; nf2++) {
                int n = warp_n * 64 + nf2 * 16 + b_row;
                uint32_t t[4];
                LDSM4(t, stg + A_BYTES + SWZ(n * 128 + kk * 32 + b_kb * 16));
                bf[nf2 * 2][0] = t[0]; bf[nf2 * 2][1] = t[1];
                bf[nf2 * 2 + 1][0] = t[2]; bf[nf2 * 2 + 1][1] = t[3];
            }
#pragma unroll
            for (int mf = 0; mf < 4; mf++)
#pragma unroll
                for (int nf = 0; nf < 8; nf++)
                    MMA16816(acc[mf][nf], a[mf], bf[nf]);
        }
    }

    // epilogue: bias (sum_e g_e * be_e) + store
#pragma unroll
    for (int mf = 0; mf < 4; mf++) {
        int rl = warp_m * 64 + mf * 16 + (lane >> 2);
        size_t row_g = (size_t)(m0 + rl);
#pragma unroll
        for (int nf = 0; nf < 8; nf++) {
            int col = warp_n * 64 + nf * 8 + (lane & 3) * 2;
            float b00 = 0.f, b01 = 0.f, b10 = 0.f, b11 = 0.f;
#pragma unroll
            for (int e = 0; e < E_; e++) {
                float gl = gs[e * BM + rl], gh = gs[e * BM + rl + 8];
                float c0 = bes[e * BN + col], c1 = bes[e * BN + col + 1];
                b00 += gl * c0; b01 += gl * c1;
                b10 += gh * c0; b11 += gh * c1;
            }
            *reinterpret_cast<float2*>(out + row_g * O_ + n0 + col) =
                make_float2(acc[mf][nf][0] + b00, acc[mf][nf][1] + b01);
            *reinterpret_cast<float2*>(out + (row_g + 8) * O_ + n0 + col) =
                make_float2(acc[mf][nf][2] + b10, acc[mf][nf][3] + b11);
        }
    }
}

// ---------------------------------------------------------------------------
extern "C" void kernel_launch(void* const* d_in, const int* in_sizes, int n_in,
                              void* d_out, int out_size) {
    const float* x  = (const float*)d_in[0];   // [8192, 1024]
    const float* Wg = (const float*)d_in[1];   // [1024, 8]
    const float* bg = (const float*)d_in[2];   // [8]
    const float* We = (const float*)d_in[3];   // [8, 1024, 1024]
    const float* be = (const float*)d_in[4];   // [8, 1024]
    float* out = (float*)d_out;                // [8192, 1024]

    cudaFuncSetAttribute(moe_fp16_kernel,
                         cudaFuncAttributeMaxDynamicSharedMemorySize, SMEM_TOTAL);

    gates_prescale_kernel<<<B_ / 8, 256>>>(x, Wg, bg);
    wt_kernel<<<dim3(O_ / 32, D_ / 32, E_), dim3(32, 8)>>>(We);

    dim3 grid(O_ / BN, B_ / BM);               // (8, 64) = 512 CTAs
    moe_fp16_kernel<<<grid, THREADS, SMEM_TOTAL>>>(be, out);
}

// round 17
// speedup vs baseline: 1.2594x; 1.0480x over previous
#include <cuda_runtime.h>
#include <cuda_fp16.h>
#include <cstdint>

// ---------------------------------------------------------------------------
// Problem constants
// ---------------------------------------------------------------------------
#define B_  8192
#define D_  1024
#define O_  1024
#define E_  8

// GEMM tiling: CTA 128x128, 4 warps of 64x64, 2 CTAs/SM.
// Stage order: kc-outer, e-inner (s = kc*8 + e). A loaded once per kc.
#define BM 128
#define BN 128
#define KSTG 64
#define NST (E_ * D_ / KSTG)        // 128 stages
#define A_BYTES (BM * 128)          // 16 KB
#define B_BYTES (BN * 128)          // 16 KB
#define THREADS 128

// SMEM layout
#define SM_GS 0                     // gates [8][128] f32 = 4 KB
#define SM_BE 4096                  // bias  [8][128] f32 = 4 KB
#define SM_A  8192                  // A double buffer: 2 x 16 KB
#define SM_B  (SM_A + 2 * A_BYTES)  // B triple buffer: 3 x 16 KB
#define SMEM_TOTAL (SM_B + 3 * B_BYTES)   // 90112 (x2 CTAs fits 228KB)

// ---------------------------------------------------------------------------
// Scratch (device globals — no allocation)
// ---------------------------------------------------------------------------
__device__ float g_gates[B_ * E_];
__device__ __align__(16) __half g_xh[(size_t)B_ * D_];   // fp16 x, single copy
__device__ __align__(16) __half g_wt[E_ * O_ * D_];      // [e][n][k] K-major

// ---------------------------------------------------------------------------
// Helpers
// ---------------------------------------------------------------------------
__device__ __forceinline__ uint32_t smem_u32(const void* p) {
    uint32_t a;
    asm("{ .reg .u64 t; cvta.to.shared.u64 t, %1; cvt.u32.u64 %0, t; }" : "=r"(a) : "l"(p));
    return a;
}
#define SWZ(x) ((x) ^ (((x) >> 3) & 0x70))

__device__ __forceinline__ void cpa16(uint32_t dst, const void* src) {
    asm volatile("cp.async.cg.shared.global [%0], [%1], 16;" :: "r"(dst), "l"(src) : "memory");
}

#define LDSM4(r, addr) \
    asm volatile("ldmatrix.sync.aligned.m8n8.x4.shared.b16 {%0,%1,%2,%3}, [%4];" \
        : "=r"((r)[0]), "=r"((r)[1]), "=r"((r)[2]), "=r"((r)[3]) : "r"(addr))

#define MMA16816(c, a, b) \
    asm volatile("mma.sync.aligned.m16n8k16.row.col.f32.f16.f16.f32 " \
        "{%0,%1,%2,%3}, {%4,%5,%6,%7}, {%8,%9}, {%0,%1,%2,%3};" \
        : "+f"((c)[0]), "+f"((c)[1]), "+f"((c)[2]), "+f"((c)[3]) \
        : "r"((a)[0]), "r"((a)[1]), "r"((a)[2]), "r"((a)[3]), \
          "r"((b)[0]), "r"((b)[1]))

#define MULH2(d, a, b) \
    asm("mul.rn.f16x2 %0, %1, %2;" : "=r"(d) : "r"(a), "r"(b))

// ---------------------------------------------------------------------------
// Kernel 1: fused prep. Blocks [0,1024): gating + x->fp16. Blocks [1024,9216):
// We transpose + fp16 convert. Both parts are memory-bound; one launch
// overlaps them across SMs.
// ---------------------------------------------------------------------------
__global__ void prep_kernel(const float* __restrict__ x,
                            const float* __restrict__ Wg,
                            const float* __restrict__ bg,
                            const float* __restrict__ We) {
    __shared__ float t[32][33];
    if (blockIdx.x < 1024) {
        // -------- gating + xh convert (round-14 validated gating loop) -----
        int row = (blockIdx.x * blockDim.x + threadIdx.x) >> 5;
        int lane = threadIdx.x & 31;
        const float* xr = x + (size_t)row * D_;

        float acc[E_];
#pragma unroll
        for (int e = 0; e < E_; e++) acc[e] = 0.f;
        for (int d = lane; d < D_; d += 32) {
            float xv = xr[d];
            const float4* w4 = reinterpret_cast<const float4*>(Wg + d * E_);
            float4 w0 = w4[0], w1 = w4[1];
            acc[0] += xv * w0.x; acc[1] += xv * w0.y;
            acc[2] += xv * w0.z; acc[3] += xv * w0.w;
            acc[4] += xv * w1.x; acc[5] += xv * w1.y;
            acc[6] += xv * w1.z; acc[7] += xv * w1.w;
        }
#pragma unroll
        for (int e = 0; e < E_; e++)
#pragma unroll
            for (int off = 16; off; off >>= 1)
                acc[e] += __shfl_xor_sync(0xffffffffu, acc[e], off);

        if (lane == 0) {
            float m = -1e30f;
#pragma unroll
            for (int e = 0; e < E_; e++) { acc[e] += bg[e]; m = fmaxf(m, acc[e]); }
            float s = 0.f;
#pragma unroll
            for (int e = 0; e < E_; e++) { acc[e] = expf(acc[e] - m); s += acc[e]; }
            float inv = 1.f / s;
#pragma unroll
            for (int e = 0; e < E_; e++) g_gates[row * E_ + e] = acc[e] * inv;
        }

        // x -> fp16 (single ungated copy)
#pragma unroll
        for (int it = 0; it < 8; it++) {
            int idx = lane + it * 32;                    // float4 index 0..255
            float4 v = reinterpret_cast<const float4*>(xr)[idx];
            __half h[4] = { __float2half_rn(v.x), __float2half_rn(v.y),
                            __float2half_rn(v.z), __float2half_rn(v.w) };
            *reinterpret_cast<uint64_t*>(&g_xh[(size_t)row * D_ + idx * 4]) =
                *reinterpret_cast<uint64_t*>(h);
        }
    } else {
        // -------- We transpose + fp16 (validated wt kernel, re-indexed) ----
        int b = blockIdx.x - 1024;
        int n0 = (b & 31) * 32;
        int k0 = ((b >> 5) & 31) * 32;
        int e  = b >> 10;
        int tx = threadIdx.x & 31, ty = threadIdx.x >> 5;
        const float* base = We + ((size_t)e << 20);
#pragma unroll
        for (int j = 0; j < 4; j++)
            t[ty + j * 8][tx] = base[(size_t)(k0 + ty + j * 8) * O_ + n0 + tx];
        __syncthreads();
        size_t ob = ((size_t)e << 20);
#pragma unroll
        for (int j = 0; j < 4; j++)
            g_wt[ob + (size_t)(n0 + ty + j * 8) * D_ + k0 + tx] =
                __float2half_rn(t[tx][ty + j * 8]);
    }
}

// ---------------------------------------------------------------------------
// Kernel 2: fused MoE GEMM — A loaded once per kc, gates folded in registers.
//   out[b,n] = sum_{kc,e,k} (g[b][e]*xh[b][k]) * wt[e][n][k] + sum_e g*be
// ---------------------------------------------------------------------------
__global__ __launch_bounds__(THREADS, 2)
void moe_fp16_kernel(const float* __restrict__ be, float* __restrict__ out) {
    extern __shared__ char smem[];
    const uint32_t sb = smem_u32(smem);
    const int tid = threadIdx.x;
    const int lane = tid & 31;
    const int wid = tid >> 5;
    const int warp_m = wid >> 1;        // 0..1  (64-row slabs)
    const int warp_n = wid & 1;         // 0..1  (64-col slabs)
    const int m0 = blockIdx.y * BM;
    const int n0 = blockIdx.x * BN;

    float* gs  = reinterpret_cast<float*>(smem + SM_GS);   // [8][128]
    float* bes = reinterpret_cast<float*>(smem + SM_BE);   // [8][128]
    for (int i = tid; i < E_ * BM; i += THREADS)
        gs[i] = g_gates[(size_t)(m0 + (i & 127)) * E_ + (i >> 7)];
    for (int i = tid; i < E_ * BN; i += THREADS)
        bes[i] = be[(i >> 7) * O_ + n0 + (i & 127)];

    float acc[4][8][4];
#pragma unroll
    for (int a = 0; a < 4; a++)
#pragma unroll
        for (int b = 0; b < 8; b++)
#pragma unroll
            for (int c = 0; c < 4; c++) acc[a][b][c] = 0.f;

    // stage loader. Stage t: B(e = t&7, kc = t>>3); A(kc) piggybacks at e==0.
    // ALWAYS commits a group (possibly empty) so wait_group counting is exact.
    auto issue = [&](int t) {
        if (t < NST) {
            const int e = t & 7, kc = t >> 3, koff = kc * KSTG;
            const uint32_t stgB = sb + SM_B + (t % 3) * B_BYTES;
#pragma unroll
            for (int i = 0; i < 8; i++) {
                int c = tid + i * THREADS;
                int r = c >> 3, k16 = c & 7;
                cpa16(stgB + SWZ(r * 128 + k16 * 16),
                      g_wt + (((size_t)e * O_ + n0 + r) * D_ + koff + k16 * 8));
            }
            if (e == 0) {
                const uint32_t stgA = sb + SM_A + (kc & 1) * A_BYTES;
#pragma unroll
                for (int i = 0; i < 8; i++) {
                    int c = tid + i * THREADS;
                    int r = c >> 3, k16 = c & 7;
                    cpa16(stgA + SWZ(r * 128 + k16 * 16),
                          g_xh + ((size_t)(m0 + r) * D_ + koff + k16 * 8));
                }
            }
        }
        asm volatile("cp.async.commit_group;" ::: "memory");
    };

    issue(0); issue(1);

    // ldmatrix lane address components
    const int a_row = lane & 15;
    const int a_kb  = lane >> 4;
    const int b_row = (lane & 7) + ((lane >> 4) << 3);
    const int b_kb  = (lane >> 3) & 1;

    for (int s = 0; s < NST; s++) {
        asm volatile("cp.async.wait_group 1;" ::: "memory");
        __syncthreads();
        issue(s + 2);

        const int e = s & 7;
        const uint32_t stgB = sb + SM_B + (s % 3) * B_BYTES;
        const uint32_t stgA = sb + SM_A + ((s >> 3) & 1) * A_BYTES;

        // per-expert broadcast gates as fp16x2 (numerics validated round 15)
        uint32_t gh2[4][2];
#pragma unroll
        for (int mf = 0; mf < 4; mf++) {
            int rl = warp_m * 64 + mf * 16 + (lane >> 2);
            __half2 h0 = __float2half2_rn(gs[e * BM + rl]);
            __half2 h1 = __float2half2_rn(gs[e * BM + rl + 8]);
            gh2[mf][0] = *reinterpret_cast<uint32_t*>(&h0);
            gh2[mf][1] = *reinterpret_cast<uint32_t*>(&h1);
        }

#pragma unroll
        for (int kk = 0; kk < 4; kk++) {      // 4 k16 steps
            uint32_t a[4][4], bf[8][2];
#pragma unroll
            for (int mf = 0; mf < 4; mf++) {
                int row = warp_m * 64 + mf * 16 + a_row;
                LDSM4(a[mf], stgA + SWZ(row * 128 + kk * 32 + a_kb * 16));
                // fold gate: regs {0,2} = row r, regs {1,3} = row r+8
                MULH2(a[mf][0], a[mf][0], gh2[mf][0]);
                MULH2(a[mf][1], a[mf][1], gh2[mf][1]);
                MULH2(a[mf][2], a[mf][2], gh2[mf][0]);
                MULH2(a[mf][3], a[mf][3], gh2[mf][1]);
            }
#pragma unroll
            for (int nf2 = 0; nf2 < 4; nf2++) {
                int n = warp_n * 64 + nf2 * 16 + b_row;
                uint32_t t[4];
                LDSM4(t, stgB + SWZ(n * 128 + kk * 32 + b_kb * 16));
                bf[nf2 * 2][0] = t[0]; bf[nf2 * 2][1] = t[1];
                bf[nf2 * 2 + 1][0] = t[2]; bf[nf2 * 2 + 1][1] = t[3];
            }
#pragma unroll
            for (int mf = 0; mf < 4; mf++)
#pragma unroll
                for (int nf = 0; nf < 8; nf++)
                    MMA16816(acc[mf][nf], a[mf], bf[nf]);
        }
    }

    // epilogue: bias (sum_e g_e * be_e) + store
#pragma unroll
    for (int mf = 0; mf < 4; mf++) {
        int rl = warp_m * 64 + mf * 16 + (lane >> 2);
        size_t row_g = (size_t)(m0 + rl);
#pragma unroll
        for (int nf = 0; nf < 8; nf++) {
            int col = warp_n * 64 + nf * 8 + (lane & 3) * 2;
            float b00 = 0.f, b01 = 0.f, b10 = 0.f, b11 = 0.f;
#pragma unroll
            for (int e = 0; e < E_; e++) {
                float gl = gs[e * BM + rl], gh = gs[e * BM + rl + 8];
                float c0 = bes[e * BN + col], c1 = bes[e * BN + col + 1];
                b00 += gl * c0; b01 += gl * c1;
                b10 += gh * c0; b11 += gh * c1;
            }
            *reinterpret_cast<float2*>(out + row_g * O_ + n0 + col) =
                make_float2(acc[mf][nf][0] + b00, acc[mf][nf][1] + b01);
            *reinterpret_cast<float2*>(out + (row_g + 8) * O_ + n0 + col) =
                make_float2(acc[mf][nf][2] + b10, acc[mf][nf][3] + b11);
        }
    }
}

// ---------------------------------------------------------------------------
extern "C" void kernel_launch(void* const* d_in, const int* in_sizes, int n_in,
                              void* d_out, int out_size) {
    const float* x  = (const float*)d_in[0];   // [8192, 1024]
    const float* Wg = (const float*)d_in[1];   // [1024, 8]
    const float* bg = (const float*)d_in[2];   // [8]
    const float* We = (const float*)d_in[3];   // [8, 1024, 1024]
    const float* be = (const float*)d_in[4];   // [8, 1024]
    float* out = (float*)d_out;                // [8192, 1024]

    cudaFuncSetAttribute(moe_fp16_kernel,
                         cudaFuncAttributeMaxDynamicSharedMemorySize, SMEM_TOTAL);

    prep_kernel<<<1024 + 8192, 256>>>(x, Wg, bg, We);

    dim3 grid(O_ / BN, B_ / BM);               // (8, 64) = 512 CTAs
    moe_fp16_kernel<<<grid, THREADS, SMEM_TOTAL>>>(be, out);
}